// round 1
// baseline (speedup 1.0000x reference)
#include <cuda_runtime.h>
#include <cstddef>

#define N_USERS  50000
#define N_ITEMS  10000
#define N_NODES  100000
#define EMBD     64
#define VIS_DIM  2048
#define TXT_DIM  300
#define H1V      512
#define H1T      256

// ---------------- device scratch (static, no allocation) ----------------
__device__ float g_H1v[N_ITEMS * H1V];   // relu(VF @ Wv1^T + bv1)
__device__ float g_H1t[N_ITEMS * H1T];   // relu(TF @ Wt1^T + bt1)
__device__ float g_Wvd[EMBD * H1V];      // Wd @ Wv2
__device__ float g_Wtd[EMBD * H1T];      // Wd @ Wt2
__device__ float g_bvd[EMBD];
__device__ float g_btd[EMBD];
__device__ float g_ego[N_NODES * EMBD];  // layer-0 embeddings (also reused as layer-2 scratch out)
__device__ float g_cur[N_NODES * EMBD];  // layer-1 output
__device__ float g_nb [N_NODES * EMBD];  // SpMM accumulator

// ---------------- fold Wd into Wv2 / Wt2 ----------------
__global__ void prep_weights(const float* __restrict__ Wd, const float* __restrict__ bd,
                             const float* __restrict__ Wv2, const float* __restrict__ bv2,
                             const float* __restrict__ Wt2, const float* __restrict__ bt2) {
    const int COLS = H1V + H1T + 1;  // 769
    int idx = blockIdx.x * blockDim.x + threadIdx.x;
    if (idx >= EMBD * COLS) return;
    int n = idx / COLS, c = idx % COLS;
    if (c < H1V) {
        float a = 0.f;
        #pragma unroll 8
        for (int j = 0; j < EMBD; j++) a += Wd[n * EMBD + j] * Wv2[j * H1V + c];
        g_Wvd[n * H1V + c] = a;
    } else if (c < H1V + H1T) {
        int k = c - H1V;
        float a = 0.f;
        #pragma unroll 8
        for (int j = 0; j < EMBD; j++) a += Wd[n * EMBD + j] * Wt2[j * H1T + k];
        g_Wtd[n * H1T + k] = a;
    } else {
        float av = 0.f, at = 0.f;
        for (int j = 0; j < EMBD; j++) {
            av += Wd[n * EMBD + j] * bv2[j];
            at += Wd[n * EMBD + j] * bt2[j];
        }
        g_bvd[n] = av + bd[n];
        g_btd[n] = at + bd[n];
    }
}

// ---------------- SGEMM: C = relu(A @ W^T + bias) ----------------
// A [M,K] row-major, W [N,K] row-major.  BM=128, BN=64, BK=16, 256 thr, TM=8, TN=4
__global__ __launch_bounds__(256)
void sgemm_bias_relu(const float* __restrict__ A, const float* __restrict__ W,
                     const float* __restrict__ bias, float* __restrict__ C,
                     int M, int N, int K) {
    __shared__ float As[16][132];
    __shared__ float Bs[16][68];
    int bm = blockIdx.x * 128;
    int bn = blockIdx.y * 64;
    int tid = threadIdx.x;
    int tx = tid & 15;   // n
    int ty = tid >> 4;   // m
    float acc[8][4] = {};

    for (int k0 = 0; k0 < K; k0 += 16) {
        // ---- load A tile 128x16 (2 x float4 per thread) ----
        #pragma unroll
        for (int r = 0; r < 2; r++) {
            int idx = tid + r * 256;       // 0..511
            int row = idx >> 2;            // 0..127
            int kq  = (idx & 3) << 2;      // 0,4,8,12
            int gm = bm + row;
            int gk = k0 + kq;
            float4 v = make_float4(0.f, 0.f, 0.f, 0.f);
            if (gm < M) {
                if (gk + 3 < K) {
                    v = *(const float4*)(A + (size_t)gm * K + gk);
                } else {
                    float t0 = (gk + 0 < K) ? A[(size_t)gm * K + gk + 0] : 0.f;
                    float t1 = (gk + 1 < K) ? A[(size_t)gm * K + gk + 1] : 0.f;
                    float t2 = (gk + 2 < K) ? A[(size_t)gm * K + gk + 2] : 0.f;
                    float t3 = (gk + 3 < K) ? A[(size_t)gm * K + gk + 3] : 0.f;
                    v = make_float4(t0, t1, t2, t3);
                }
            }
            As[kq + 0][row] = v.x;
            As[kq + 1][row] = v.y;
            As[kq + 2][row] = v.z;
            As[kq + 3][row] = v.w;
        }
        // ---- load B tile 16x64 (1 x float4 per thread) ----
        {
            int n  = tid >> 2;             // 0..63
            int kq = (tid & 3) << 2;
            int gn = bn + n;
            int gk = k0 + kq;
            float4 v = make_float4(0.f, 0.f, 0.f, 0.f);
            if (gk + 3 < K) {
                v = *(const float4*)(W + (size_t)gn * K + gk);
            } else {
                float t0 = (gk + 0 < K) ? W[(size_t)gn * K + gk + 0] : 0.f;
                float t1 = (gk + 1 < K) ? W[(size_t)gn * K + gk + 1] : 0.f;
                float t2 = (gk + 2 < K) ? W[(size_t)gn * K + gk + 2] : 0.f;
                float t3 = (gk + 3 < K) ? W[(size_t)gn * K + gk + 3] : 0.f;
                v = make_float4(t0, t1, t2, t3);
            }
            Bs[kq + 0][n] = v.x;
            Bs[kq + 1][n] = v.y;
            Bs[kq + 2][n] = v.z;
            Bs[kq + 3][n] = v.w;
        }
        __syncthreads();
        #pragma unroll
        for (int kk = 0; kk < 16; kk++) {
            float4 a0 = *(const float4*)&As[kk][ty * 8];
            float4 a1 = *(const float4*)&As[kk][ty * 8 + 4];
            float4 b  = *(const float4*)&Bs[kk][tx * 4];
            float am[8] = {a0.x, a0.y, a0.z, a0.w, a1.x, a1.y, a1.z, a1.w};
            float bn4[4] = {b.x, b.y, b.z, b.w};
            #pragma unroll
            for (int i = 0; i < 8; i++)
                #pragma unroll
                for (int j = 0; j < 4; j++)
                    acc[i][j] += am[i] * bn4[j];
        }
        __syncthreads();
    }
    // ---- epilogue: bias + relu ----
    #pragma unroll
    for (int i = 0; i < 8; i++) {
        int gm = bm + ty * 8 + i;
        if (gm >= M) continue;
        #pragma unroll
        for (int j = 0; j < 4; j++) {
            int gn = bn + tx * 4 + j;
            float v = acc[i][j] + bias[gn];
            v = v > 0.f ? v : 0.f;
            C[(size_t)gm * N + gn] = v;
        }
    }
}

// ---------------- copy user/entity embeddings into ego + out[:,0:64] ----------------
__global__ void ego_init(const float4* __restrict__ emb, float* __restrict__ out) {
    int idx = blockIdx.x * blockDim.x + threadIdx.x;
    if (idx >= N_NODES * 16) return;
    int r = idx >> 4, c = idx & 15;
    if (r >= N_USERS && r < N_USERS + N_ITEMS) return;  // items written by fuse_items
    float4 v = emb[idx];
    ((float4*)g_ego)[idx] = v;
    *(float4*)(out + (size_t)r * 192 + c * 4) = v;
}

// ---------------- fused_item = 0.5*(H1v@Wvd^T + bvd + H1t@Wtd^T + btd) ----------------
// BM=64, BN=64(all), BK=16, 256 thr, TM=4, TN=4.  Writes ego item rows + out[:,0:64].
__global__ __launch_bounds__(256)
void fuse_items(float* __restrict__ out) {
    __shared__ float As[16][68];
    __shared__ float Bs[16][68];
    int bm = blockIdx.x * 64;
    int tid = threadIdx.x;
    int tx = tid & 15, ty = tid >> 4;
    int lrow = tid >> 2;            // 0..63
    int lkq  = (tid & 3) << 2;      // 0,4,8,12
    float acc[4][4] = {};

    #pragma unroll
    for (int phase = 0; phase < 2; phase++) {
        const float* A = phase ? g_H1t : g_H1v;
        const float* W = phase ? g_Wtd : g_Wvd;
        int K = phase ? H1T : H1V;
        for (int k0 = 0; k0 < K; k0 += 16) {
            int gm = bm + lrow;
            float4 va = make_float4(0.f, 0.f, 0.f, 0.f);
            if (gm < N_ITEMS) va = *(const float4*)(A + (size_t)gm * K + k0 + lkq);
            As[lkq + 0][lrow] = va.x;
            As[lkq + 1][lrow] = va.y;
            As[lkq + 2][lrow] = va.z;
            As[lkq + 3][lrow] = va.w;
            float4 vb = *(const float4*)(W + (size_t)lrow * K + k0 + lkq);
            Bs[lkq + 0][lrow] = vb.x;
            Bs[lkq + 1][lrow] = vb.y;
            Bs[lkq + 2][lrow] = vb.z;
            Bs[lkq + 3][lrow] = vb.w;
            __syncthreads();
            #pragma unroll
            for (int kk = 0; kk < 16; kk++) {
                float4 a = *(const float4*)&As[kk][ty * 4];
                float4 b = *(const float4*)&Bs[kk][tx * 4];
                float am[4] = {a.x, a.y, a.z, a.w};
                float bn4[4] = {b.x, b.y, b.z, b.w};
                #pragma unroll
                for (int i = 0; i < 4; i++)
                    #pragma unroll
                    for (int j = 0; j < 4; j++)
                        acc[i][j] += am[i] * bn4[j];
            }
            __syncthreads();
        }
    }
    #pragma unroll
    for (int i = 0; i < 4; i++) {
        int gm = bm + ty * 4 + i;
        if (gm >= N_ITEMS) continue;
        #pragma unroll
        for (int j = 0; j < 4; j++) {
            int gn = tx * 4 + j;
            float v = 0.5f * (acc[i][j] + g_bvd[gn] + g_btd[gn]);
            g_ego[(size_t)(N_USERS + gm) * 64 + gn] = v;
            out[(size_t)(N_USERS + gm) * 192 + gn] = v;
        }
    }
}

// ---------------- zero the SpMM accumulator ----------------
__global__ void zero_nb() {
    int idx = blockIdx.x * blockDim.x + threadIdx.x;
    if (idx < N_NODES * 16) ((float4*)g_nb)[idx] = make_float4(0.f, 0.f, 0.f, 0.f);
}

// ---------------- SpMM: nb[row] += val * cur[col], 16 lanes/edge, float4 atomics ----------------
__global__ void spmm_atomic(const int* __restrict__ arow, const int* __restrict__ acol,
                            const float* __restrict__ aval, const float4* __restrict__ cur,
                            float4* __restrict__ nb, int nnz) {
    int idx = blockIdx.x * blockDim.x + threadIdx.x;
    int e = idx >> 4, l = idx & 15;
    if (e >= nnz) return;
    int r = arow[e];
    int c = acol[e];
    float v = aval[e];
    float4 x = cur[(size_t)c * 16 + l];
    float4 m = make_float4(v * x.x, v * x.y, v * x.z, v * x.w);
#if __CUDA_ARCH__ >= 900
    atomicAdd(nb + (size_t)r * 16 + l, m);
#else
    float* p = (float*)(nb + (size_t)r * 16 + l);
    atomicAdd(p + 0, m.x);
    atomicAdd(p + 1, m.y);
    atomicAdd(p + 2, m.z);
    atomicAdd(p + 3, m.w);
#endif
}

// ---------------- dense layer: next = leaky_relu([cur|nb] @ Wc^T + bc) ----------------
// BM=64, N=64, K=128 (two 64-phases), 256 thr, TM=4, TN=4.
__global__ __launch_bounds__(256)
void dense_layer(const float* __restrict__ cur, const float* __restrict__ nb,
                 const float* __restrict__ Wc, const float* __restrict__ bc,
                 float* __restrict__ curout, float* __restrict__ out, int outOff) {
    __shared__ float As[16][68];
    __shared__ float Bs[16][68];
    int bm = blockIdx.x * 64;
    int tid = threadIdx.x;
    int tx = tid & 15, ty = tid >> 4;
    int lrow = tid >> 2, lkq = (tid & 3) << 2;
    float acc[4][4] = {};

    #pragma unroll
    for (int phase = 0; phase < 2; phase++) {
        const float* A = phase ? nb : cur;
        int koff = phase ? 64 : 0;
        #pragma unroll
        for (int k0 = 0; k0 < 64; k0 += 16) {
            int gm = bm + lrow;
            float4 va = (gm < N_NODES) ? *(const float4*)(A + (size_t)gm * 64 + k0 + lkq)
                                       : make_float4(0.f, 0.f, 0.f, 0.f);
            As[lkq + 0][lrow] = va.x;
            As[lkq + 1][lrow] = va.y;
            As[lkq + 2][lrow] = va.z;
            As[lkq + 3][lrow] = va.w;
            float4 vb = *(const float4*)(Wc + (size_t)lrow * 128 + koff + k0 + lkq);
            Bs[lkq + 0][lrow] = vb.x;
            Bs[lkq + 1][lrow] = vb.y;
            Bs[lkq + 2][lrow] = vb.z;
            Bs[lkq + 3][lrow] = vb.w;
            __syncthreads();
            #pragma unroll
            for (int kk = 0; kk < 16; kk++) {
                float4 a = *(const float4*)&As[kk][ty * 4];
                float4 b = *(const float4*)&Bs[kk][tx * 4];
                float am[4] = {a.x, a.y, a.z, a.w};
                float bn4[4] = {b.x, b.y, b.z, b.w};
                #pragma unroll
                for (int i = 0; i < 4; i++)
                    #pragma unroll
                    for (int j = 0; j < 4; j++)
                        acc[i][j] += am[i] * bn4[j];
            }
            __syncthreads();
        }
    }
    #pragma unroll
    for (int i = 0; i < 4; i++) {
        int gm = bm + ty * 4 + i;
        if (gm >= N_NODES) continue;
        #pragma unroll
        for (int j = 0; j < 4; j++) {
            int gn = tx * 4 + j;
            float v = acc[i][j] + bc[gn];
            v = v > 0.f ? v : 0.01f * v;  // leaky_relu, slope 0.01
            curout[(size_t)gm * 64 + gn] = v;
            out[(size_t)gm * 192 + outOff + gn] = v;
        }
    }
}

// ---------------- launch ----------------
extern "C" void kernel_launch(void* const* d_in, const int* in_sizes, int n_in,
                              void* d_out, int out_size) {
    const int*   adj_row = (const int*)d_in[0];
    const int*   adj_col = (const int*)d_in[1];
    const float* adj_val = (const float*)d_in[2];
    const float* emb     = (const float*)d_in[3];
    const float* vf      = (const float*)d_in[4];
    const float* tf      = (const float*)d_in[5];
    const float* Wv1 = (const float*)d_in[6],  *bv1 = (const float*)d_in[7];
    const float* Wv2 = (const float*)d_in[8],  *bv2 = (const float*)d_in[9];
    const float* Wt1 = (const float*)d_in[10], *bt1 = (const float*)d_in[11];
    const float* Wt2 = (const float*)d_in[12], *bt2 = (const float*)d_in[13];
    const float* Wd  = (const float*)d_in[14], *bd  = (const float*)d_in[15];
    const float* Wc0 = (const float*)d_in[16], *bc0 = (const float*)d_in[17];
    const float* Wc1 = (const float*)d_in[18], *bc1 = (const float*)d_in[19];
    float* out = (float*)d_out;
    int nnz = in_sizes[0];

    float *p_h1v, *p_h1t, *p_ego, *p_cur, *p_nb;
    cudaGetSymbolAddress((void**)&p_h1v, g_H1v);
    cudaGetSymbolAddress((void**)&p_h1t, g_H1t);
    cudaGetSymbolAddress((void**)&p_ego, g_ego);
    cudaGetSymbolAddress((void**)&p_cur, g_cur);
    cudaGetSymbolAddress((void**)&p_nb,  g_nb);

    // fold Wd into the second-layer MLP weights
    prep_weights<<<(EMBD * (H1V + H1T + 1) + 255) / 256, 256>>>(Wd, bd, Wv2, bv2, Wt2, bt2);

    // item feature MLP layer 1 (the big GEMM) + text layer 1
    sgemm_bias_relu<<<dim3((N_ITEMS + 127) / 128, H1V / 64), 256>>>(vf, Wv1, bv1, p_h1v,
                                                                    N_ITEMS, H1V, VIS_DIM);
    sgemm_bias_relu<<<dim3((N_ITEMS + 127) / 128, H1T / 64), 256>>>(tf, Wt1, bt1, p_h1t,
                                                                    N_ITEMS, H1T, TXT_DIM);

    // ego graph: original embeddings for users/entities, fused multimodal for items
    ego_init<<<(N_NODES * 16 + 255) / 256, 256>>>((const float4*)emb, out);
    fuse_items<<<(N_ITEMS + 63) / 64, 256>>>(out);

    int spmm_blocks = (nnz * 16 + 255) / 256;

    // layer 0: ego -> cur
    zero_nb<<<(N_NODES * 16 + 255) / 256, 256>>>();
    spmm_atomic<<<spmm_blocks, 256>>>(adj_row, adj_col, adj_val,
                                      (const float4*)p_ego, (float4*)p_nb, nnz);
    dense_layer<<<(N_NODES + 63) / 64, 256>>>(p_ego, p_nb, Wc0, bc0, p_cur, out, 64);

    // layer 1: cur -> out[:,128:192] (scratch buffer = g_ego, no longer needed)
    zero_nb<<<(N_NODES * 16 + 255) / 256, 256>>>();
    spmm_atomic<<<spmm_blocks, 256>>>(adj_row, adj_col, adj_val,
                                      (const float4*)p_cur, (float4*)p_nb, nnz);
    dense_layer<<<(N_NODES + 63) / 64, 256>>>(p_cur, p_nb, Wc1, bc1, p_ego, out, 128);
}

// round 3
// speedup vs baseline: 1.5934x; 1.5934x over previous
#include <cuda_runtime.h>
#include <cuda_bf16.h>
#include <cstdint>
#include <cstddef>

#define N_USERS  50000
#define N_ITEMS  10000
#define N_NODES  100000
#define EMBD     64
#define VIS_DIM  2048
#define TXT_DIM  300
#define H1V      512
#define H1T      256

#define M_PAD    10112          // 79 * 128
#define K3_VIS   (3 * 2048)     // 6144
#define KP_TXT   320            // 300 padded to 320
#define K3_TXT   (3 * KP_TXT)   // 960

// ---------------- device scratch (static, no allocation) ----------------
__device__ float g_H1v[N_ITEMS * H1V];
__device__ float g_H1t[N_ITEMS * H1T];
__device__ float g_Wvd[EMBD * H1V];
__device__ float g_Wtd[EMBD * H1T];
__device__ float g_bvd[EMBD];
__device__ float g_btd[EMBD];
__device__ float g_ego[N_NODES * EMBD];
__device__ float g_cur[N_NODES * EMBD];
__device__ float g_nb [N_NODES * EMBD];
// bf16x3-split operand buffers
__device__ __nv_bfloat16 g_Av[(size_t)M_PAD * K3_VIS];
__device__ __nv_bfloat16 g_Bv[(size_t)H1V  * K3_VIS];
__device__ __nv_bfloat16 g_At[(size_t)M_PAD * K3_TXT];
__device__ __nv_bfloat16 g_Bt[(size_t)H1T  * K3_TXT];

// ================= PTX helpers (sm_80+ features only) =================
__device__ __forceinline__ uint32_t smem_u32(const void* p) {
    uint32_t a;
    asm("{ .reg .u64 t; cvta.to.shared.u64 t, %1; cvt.u32.u64 %0, t; }" : "=r"(a) : "l"(p));
    return a;
}
__device__ __forceinline__ void cp_async16(uint32_t s, const void* g) {
    asm volatile("cp.async.cg.shared.global [%0], [%1], 16;" :: "r"(s), "l"(g));
}
__device__ __forceinline__ void cp_commit() { asm volatile("cp.async.commit_group;"); }
template<int N> __device__ __forceinline__ void cp_wait() {
    asm volatile("cp.async.wait_group %0;" :: "n"(N));
}
__device__ __forceinline__ void ldm_x4(uint32_t* r, uint32_t addr) {
    asm volatile("ldmatrix.sync.aligned.m8n8.x4.shared.b16 {%0,%1,%2,%3}, [%4];"
                 : "=r"(r[0]), "=r"(r[1]), "=r"(r[2]), "=r"(r[3]) : "r"(addr));
}
__device__ __forceinline__ void mma16816(float* d, const uint32_t* a, uint32_t b0, uint32_t b1) {
    asm volatile("mma.sync.aligned.m16n8k16.row.col.f32.bf16.bf16.f32 "
                 "{%0,%1,%2,%3}, {%4,%5,%6,%7}, {%8,%9}, {%0,%1,%2,%3};"
                 : "+f"(d[0]), "+f"(d[1]), "+f"(d[2]), "+f"(d[3])
                 : "r"(a[0]), "r"(a[1]), "r"(a[2]), "r"(a[3]), "r"(b0), "r"(b1));
}
// smem tile layout: [128 rows][32 bf16] = row*64B, 4x16B chunks, XOR swizzle
__device__ __forceinline__ uint32_t toff(int r, int c) {
    return (uint32_t)((r << 6) + (((c) ^ ((r >> 1) & 3)) << 4));
}

// ---------------- fp32 -> bf16x3 split ----------------
__global__ void convert_split3(const float* __restrict__ src, __nv_bfloat16* __restrict__ dst,
                               int Msrc, int Mpad, int Ksrc, int Kpad) {
    int Kp2 = Kpad >> 1;
    int idx = blockIdx.x * blockDim.x + threadIdx.x;
    if (idx >= Mpad * Kp2) return;
    int m = idx / Kp2, kq = idx % Kp2;
    float2 v = make_float2(0.f, 0.f);
    if (m < Msrc && 2 * kq + 1 < Ksrc)
        v = *(const float2*)(src + (size_t)m * Ksrc + 2 * kq);
    __nv_bfloat16 hx = __float2bfloat16(v.x), hy = __float2bfloat16(v.y);
    __nv_bfloat162 hi; hi.x = hx; hi.y = hy;
    __nv_bfloat162 lo;
    lo.x = __float2bfloat16(v.x - __bfloat162float(hx));
    lo.y = __float2bfloat16(v.y - __bfloat162float(hy));
    __nv_bfloat162* d = (__nv_bfloat162*)dst + (size_t)m * (3 * Kp2) + kq;
    d[0] = hi;
    d[Kp2] = lo;
    d[2 * Kp2] = hi;
}
__global__ void convert_split3_b(const float* __restrict__ src, __nv_bfloat16* __restrict__ dst,
                                 int Msrc, int Ksrc, int Kpad) {
    int Kp2 = Kpad >> 1;
    int idx = blockIdx.x * blockDim.x + threadIdx.x;
    if (idx >= Msrc * Kp2) return;
    int m = idx / Kp2, kq = idx % Kp2;
    float2 v = make_float2(0.f, 0.f);
    if (2 * kq + 1 < Ksrc)
        v = *(const float2*)(src + (size_t)m * Ksrc + 2 * kq);
    __nv_bfloat16 hx = __float2bfloat16(v.x), hy = __float2bfloat16(v.y);
    __nv_bfloat162 hi; hi.x = hx; hi.y = hy;
    __nv_bfloat162 lo;
    lo.x = __float2bfloat16(v.x - __bfloat162float(hx));
    lo.y = __float2bfloat16(v.y - __bfloat162float(hy));
    __nv_bfloat162* d = (__nv_bfloat162*)dst + (size_t)m * (3 * Kp2) + kq;
    d[0] = hi;
    d[Kp2] = hi;
    d[2 * Kp2] = lo;
}

// ---------------- mma.sync bf16 GEMM: C = relu(A' @ B'^T + bias) ----------------
// BM=BN=128, BK=32, 4-stage cp.async pipeline, 256 threads, warp tile 64x32.
#define GSTG 4
#define TILE_B 8192
#define STAGE_B (2 * TILE_B)
#define GSMEM (GSTG * STAGE_B)

__global__ __launch_bounds__(256)
void gemm_mma_bf16(const __nv_bfloat16* __restrict__ A, const __nv_bfloat16* __restrict__ B,
                   const float* __restrict__ bias, float* __restrict__ C,
                   int M, int Ntot, int GK, int niter) {
    extern __shared__ char smem[];
    uint32_t sbase = smem_u32(smem);
    int tid = threadIdx.x;
    int bm = blockIdx.x * 128, bn = blockIdx.y * 128;

    // ---- load descriptors: 4 x 16B per thread per tile-pair ----
    int r0 = tid >> 2, c0 = tid & 3;   // rows 0-63
    int r1 = r0 + 64;                  // rows 64-127
    const char* gA0 = (const char*)(A + (size_t)(bm + r0) * GK) + c0 * 16;
    const char* gA1 = (const char*)(A + (size_t)(bm + r1) * GK) + c0 * 16;
    const char* gB0 = (const char*)(B + (size_t)(bn + r0) * GK) + c0 * 16;
    const char* gB1 = (const char*)(B + (size_t)(bn + r1) * GK) + c0 * 16;
    uint32_t o0 = toff(r0, c0), o1 = toff(r1, c0);

    // ---- warp compute coords ----
    int w = tid >> 5, lane = tid & 31;
    int wm = w & 1, wn = w >> 1;          // warp tile: rows wm*64, cols wn*32
    int lrow = lane & 15, lchk = lane >> 4;
    float acc[4][4][4];
    #pragma unroll
    for (int i = 0; i < 4; i++)
        #pragma unroll
        for (int j = 0; j < 4; j++)
            #pragma unroll
            for (int q = 0; q < 4; q++) acc[i][j][q] = 0.f;

    // ---- preload stages 0..GSTG-2 ----
    #pragma unroll
    for (int s = 0; s < GSTG - 1; s++) {
        if (s < niter) {
            uint32_t sb = sbase + s * STAGE_B;
            size_t go = (size_t)s * 64;
            cp_async16(sb + o0, gA0 + go);
            cp_async16(sb + o1, gA1 + go);
            cp_async16(sb + TILE_B + o0, gB0 + go);
            cp_async16(sb + TILE_B + o1, gB1 + go);
        }
        cp_commit();
    }

    for (int it = 0; it < niter; it++) {
        cp_wait<GSTG - 2>();
        __syncthreads();
        // prefetch tile it+GSTG-1
        {
            int pf = it + GSTG - 1;
            if (pf < niter) {
                uint32_t sb = sbase + (pf & (GSTG - 1)) * STAGE_B;
                size_t go = (size_t)pf * 64;
                cp_async16(sb + o0, gA0 + go);
                cp_async16(sb + o1, gA1 + go);
                cp_async16(sb + TILE_B + o0, gB0 + go);
                cp_async16(sb + TILE_B + o1, gB1 + go);
            }
            cp_commit();
        }
        // compute on slot it%GSTG
        uint32_t sA = sbase + (it & (GSTG - 1)) * STAGE_B;
        uint32_t sB = sA + TILE_B;
        #pragma unroll
        for (int ks = 0; ks < 2; ks++) {
            uint32_t Ar[4][4], Br[2][4];
            #pragma unroll
            for (int mi = 0; mi < 4; mi++)
                ldm_x4(Ar[mi], sA + toff(wm * 64 + mi * 16 + lrow, ks * 2 + lchk));
            #pragma unroll
            for (int nj = 0; nj < 2; nj++)
                ldm_x4(Br[nj], sB + toff(wn * 32 + nj * 16 + lrow, ks * 2 + lchk));
            #pragma unroll
            for (int mi = 0; mi < 4; mi++)
                #pragma unroll
                for (int n = 0; n < 4; n++)
                    mma16816(acc[mi][n], Ar[mi], Br[n >> 1][n & 1], Br[n >> 1][2 + (n & 1)]);
        }
    }

    // ---- epilogue: bias + relu ----
    int g = lane >> 2, tig = lane & 3;
    #pragma unroll
    for (int mi = 0; mi < 4; mi++) {
        int gm0 = bm + wm * 64 + mi * 16 + g;
        #pragma unroll
        for (int n = 0; n < 4; n++) {
            int gn = bn + wn * 32 + n * 8 + tig * 2;
            float2 bb = *(const float2*)(bias + gn);
            if (gm0 < M) {
                float2 v;
                v.x = fmaxf(acc[mi][n][0] + bb.x, 0.f);
                v.y = fmaxf(acc[mi][n][1] + bb.y, 0.f);
                *(float2*)(C + (size_t)gm0 * Ntot + gn) = v;
            }
            if (gm0 + 8 < M) {
                float2 v;
                v.x = fmaxf(acc[mi][n][2] + bb.x, 0.f);
                v.y = fmaxf(acc[mi][n][3] + bb.y, 0.f);
                *(float2*)(C + (size_t)(gm0 + 8) * Ntot + gn) = v;
            }
        }
    }
}

// ---------------- fold Wd into Wv2 / Wt2 ----------------
__global__ void prep_weights(const float* __restrict__ Wd, const float* __restrict__ bd,
                             const float* __restrict__ Wv2, const float* __restrict__ bv2,
                             const float* __restrict__ Wt2, const float* __restrict__ bt2) {
    const int COLS = H1V + H1T + 1;
    int idx = blockIdx.x * blockDim.x + threadIdx.x;
    if (idx >= EMBD * COLS) return;
    int n = idx / COLS, c = idx % COLS;
    if (c < H1V) {
        float a = 0.f;
        #pragma unroll 8
        for (int j = 0; j < EMBD; j++) a += Wd[n * EMBD + j] * Wv2[j * H1V + c];
        g_Wvd[n * H1V + c] = a;
    } else if (c < H1V + H1T) {
        int k = c - H1V;
        float a = 0.f;
        #pragma unroll 8
        for (int j = 0; j < EMBD; j++) a += Wd[n * EMBD + j] * Wt2[j * H1T + k];
        g_Wtd[n * H1T + k] = a;
    } else {
        float av = 0.f, at = 0.f;
        for (int j = 0; j < EMBD; j++) {
            av += Wd[n * EMBD + j] * bv2[j];
            at += Wd[n * EMBD + j] * bt2[j];
        }
        g_bvd[n] = av + bd[n];
        g_btd[n] = at + bd[n];
    }
}

// ---------------- copy user/entity embeddings into ego + out[:,0:64] ----------------
__global__ void ego_init(const float4* __restrict__ emb, float* __restrict__ out) {
    int idx = blockIdx.x * blockDim.x + threadIdx.x;
    if (idx >= N_NODES * 16) return;
    int r = idx >> 4, c = idx & 15;
    if (r >= N_USERS && r < N_USERS + N_ITEMS) return;
    float4 v = emb[idx];
    ((float4*)g_ego)[idx] = v;
    *(float4*)(out + (size_t)r * 192 + c * 4) = v;
}

// ---------------- fused_item = 0.5*(H1v@Wvd^T + bvd + H1t@Wtd^T + btd) ----------------
__global__ __launch_bounds__(256)
void fuse_items(float* __restrict__ out) {
    __shared__ float As[16][68];
    __shared__ float Bs[16][68];
    int bm = blockIdx.x * 64;
    int tid = threadIdx.x;
    int tx = tid & 15, ty = tid >> 4;
    int lrow = tid >> 2, lkq = (tid & 3) << 2;
    float acc[4][4] = {};

    #pragma unroll
    for (int phase = 0; phase < 2; phase++) {
        const float* A = phase ? g_H1t : g_H1v;
        const float* W = phase ? g_Wtd : g_Wvd;
        int K = phase ? H1T : H1V;
        for (int k0 = 0; k0 < K; k0 += 16) {
            int gm = bm + lrow;
            float4 va = make_float4(0.f, 0.f, 0.f, 0.f);
            if (gm < N_ITEMS) va = *(const float4*)(A + (size_t)gm * K + k0 + lkq);
            As[lkq + 0][lrow] = va.x;
            As[lkq + 1][lrow] = va.y;
            As[lkq + 2][lrow] = va.z;
            As[lkq + 3][lrow] = va.w;
            float4 vb = *(const float4*)(W + (size_t)lrow * K + k0 + lkq);
            Bs[lkq + 0][lrow] = vb.x;
            Bs[lkq + 1][lrow] = vb.y;
            Bs[lkq + 2][lrow] = vb.z;
            Bs[lkq + 3][lrow] = vb.w;
            __syncthreads();
            #pragma unroll
            for (int kk = 0; kk < 16; kk++) {
                float4 a = *(const float4*)&As[kk][ty * 4];
                float4 b = *(const float4*)&Bs[kk][tx * 4];
                float am[4] = {a.x, a.y, a.z, a.w};
                float bn4[4] = {b.x, b.y, b.z, b.w};
                #pragma unroll
                for (int i = 0; i < 4; i++)
                    #pragma unroll
                    for (int j = 0; j < 4; j++)
                        acc[i][j] += am[i] * bn4[j];
            }
            __syncthreads();
        }
    }
    #pragma unroll
    for (int i = 0; i < 4; i++) {
        int gm = bm + ty * 4 + i;
        if (gm >= N_ITEMS) continue;
        #pragma unroll
        for (int j = 0; j < 4; j++) {
            int gn = tx * 4 + j;
            float v = 0.5f * (acc[i][j] + g_bvd[gn] + g_btd[gn]);
            g_ego[(size_t)(N_USERS + gm) * 64 + gn] = v;
            out[(size_t)(N_USERS + gm) * 192 + gn] = v;
        }
    }
}

// ---------------- zero the SpMM accumulator ----------------
__global__ void zero_nb() {
    int idx = blockIdx.x * blockDim.x + threadIdx.x;
    if (idx < N_NODES * 16) ((float4*)g_nb)[idx] = make_float4(0.f, 0.f, 0.f, 0.f);
}

// ---------------- SpMM: nb[row] += val * cur[col] ----------------
__global__ void spmm_atomic(const int* __restrict__ arow, const int* __restrict__ acol,
                            const float* __restrict__ aval, const float4* __restrict__ cur,
                            float4* __restrict__ nb, int nnz) {
    int idx = blockIdx.x * blockDim.x + threadIdx.x;
    int e = idx >> 4, l = idx & 15;
    if (e >= nnz) return;
    int r = arow[e];
    int c = acol[e];
    float v = aval[e];
    float4 x = cur[(size_t)c * 16 + l];
    float4 m = make_float4(v * x.x, v * x.y, v * x.z, v * x.w);
#if __CUDA_ARCH__ >= 900
    atomicAdd(nb + (size_t)r * 16 + l, m);
#else
    float* p = (float*)(nb + (size_t)r * 16 + l);
    atomicAdd(p + 0, m.x);
    atomicAdd(p + 1, m.y);
    atomicAdd(p + 2, m.z);
    atomicAdd(p + 3, m.w);
#endif
}

// ---------------- dense layer: next = leaky_relu([cur|nb] @ Wc^T + bc) ----------------
__global__ __launch_bounds__(256)
void dense_layer(const float* __restrict__ cur, const float* __restrict__ nb,
                 const float* __restrict__ Wc, const float* __restrict__ bc,
                 float* __restrict__ curout, float* __restrict__ out, int outOff) {
    __shared__ float As[16][68];
    __shared__ float Bs[16][68];
    int bm = blockIdx.x * 64;
    int tid = threadIdx.x;
    int tx = tid & 15, ty = tid >> 4;
    int lrow = tid >> 2, lkq = (tid & 3) << 2;
    float acc[4][4] = {};

    #pragma unroll
    for (int phase = 0; phase < 2; phase++) {
        const float* A = phase ? nb : cur;
        int koff = phase ? 64 : 0;
        #pragma unroll
        for (int k0 = 0; k0 < 64; k0 += 16) {
            int gm = bm + lrow;
            float4 va = (gm < N_NODES) ? *(const float4*)(A + (size_t)gm * 64 + k0 + lkq)
                                       : make_float4(0.f, 0.f, 0.f, 0.f);
            As[lkq + 0][lrow] = va.x;
            As[lkq + 1][lrow] = va.y;
            As[lkq + 2][lrow] = va.z;
            As[lkq + 3][lrow] = va.w;
            float4 vb = *(const float4*)(Wc + (size_t)lrow * 128 + koff + k0 + lkq);
            Bs[lkq + 0][lrow] = vb.x;
            Bs[lkq + 1][lrow] = vb.y;
            Bs[lkq + 2][lrow] = vb.z;
            Bs[lkq + 3][lrow] = vb.w;
            __syncthreads();
            #pragma unroll
            for (int kk = 0; kk < 16; kk++) {
                float4 a = *(const float4*)&As[kk][ty * 4];
                float4 b = *(const float4*)&Bs[kk][tx * 4];
                float am[4] = {a.x, a.y, a.z, a.w};
                float bn4[4] = {b.x, b.y, b.z, b.w};
                #pragma unroll
                for (int i = 0; i < 4; i++)
                    #pragma unroll
                    for (int j = 0; j < 4; j++)
                        acc[i][j] += am[i] * bn4[j];
            }
            __syncthreads();
        }
    }
    #pragma unroll
    for (int i = 0; i < 4; i++) {
        int gm = bm + ty * 4 + i;
        if (gm >= N_NODES) continue;
        #pragma unroll
        for (int j = 0; j < 4; j++) {
            int gn = tx * 4 + j;
            float v = acc[i][j] + bc[gn];
            v = v > 0.f ? v : 0.01f * v;
            curout[(size_t)gm * 64 + gn] = v;
            out[(size_t)gm * 192 + outOff + gn] = v;
        }
    }
}

// ---------------- launch ----------------
extern "C" void kernel_launch(void* const* d_in, const int* in_sizes, int n_in,
                              void* d_out, int out_size) {
    const int*   adj_row = (const int*)d_in[0];
    const int*   adj_col = (const int*)d_in[1];
    const float* adj_val = (const float*)d_in[2];
    const float* emb     = (const float*)d_in[3];
    const float* vf      = (const float*)d_in[4];
    const float* tf      = (const float*)d_in[5];
    const float* Wv1 = (const float*)d_in[6],  *bv1 = (const float*)d_in[7];
    const float* Wv2 = (const float*)d_in[8],  *bv2 = (const float*)d_in[9];
    const float* Wt1 = (const float*)d_in[10], *bt1 = (const float*)d_in[11];
    const float* Wt2 = (const float*)d_in[12], *bt2 = (const float*)d_in[13];
    const float* Wd  = (const float*)d_in[14], *bd  = (const float*)d_in[15];
    const float* Wc0 = (const float*)d_in[16], *bc0 = (const float*)d_in[17];
    const float* Wc1 = (const float*)d_in[18], *bc1 = (const float*)d_in[19];
    float* out = (float*)d_out;
    int nnz = in_sizes[0];

    float *p_h1v, *p_h1t, *p_ego, *p_cur, *p_nb;
    __nv_bfloat16 *p_Av, *p_Bv, *p_At, *p_Bt;
    cudaGetSymbolAddress((void**)&p_h1v, g_H1v);
    cudaGetSymbolAddress((void**)&p_h1t, g_H1t);
    cudaGetSymbolAddress((void**)&p_ego, g_ego);
    cudaGetSymbolAddress((void**)&p_cur, g_cur);
    cudaGetSymbolAddress((void**)&p_nb,  g_nb);
    cudaGetSymbolAddress((void**)&p_Av,  g_Av);
    cudaGetSymbolAddress((void**)&p_Bv,  g_Bv);
    cudaGetSymbolAddress((void**)&p_At,  g_At);
    cudaGetSymbolAddress((void**)&p_Bt,  g_Bt);

    cudaFuncSetAttribute(gemm_mma_bf16, cudaFuncAttributeMaxDynamicSharedMemorySize, GSMEM);

    // fold Wd into the second-layer MLP weights
    prep_weights<<<(EMBD * (H1V + H1T + 1) + 255) / 256, 256>>>(Wd, bd, Wv2, bv2, Wt2, bt2);

    // split fp32 operands into bf16 hi/lo triple-K layout
    convert_split3<<<((size_t)M_PAD * (2048 / 2) + 255) / 256, 256>>>(vf, p_Av, N_ITEMS, M_PAD, VIS_DIM, 2048);
    convert_split3_b<<<((size_t)H1V * (2048 / 2) + 255) / 256, 256>>>(Wv1, p_Bv, H1V, VIS_DIM, 2048);
    convert_split3<<<((size_t)M_PAD * (KP_TXT / 2) + 255) / 256, 256>>>(tf, p_At, N_ITEMS, M_PAD, TXT_DIM, KP_TXT);
    convert_split3_b<<<((size_t)H1T * (KP_TXT / 2) + 255) / 256, 256>>>(Wt1, p_Bt, H1T, TXT_DIM, KP_TXT);

    // tensor-core GEMMs (mma.sync bf16, fp32-emulated via 3-way split)
    gemm_mma_bf16<<<dim3(M_PAD / 128, H1V / 128), 256, GSMEM>>>(p_Av, p_Bv, bv1, p_h1v,
                                                                 N_ITEMS, H1V, K3_VIS, K3_VIS / 32);
    gemm_mma_bf16<<<dim3(M_PAD / 128, H1T / 128), 256, GSMEM>>>(p_At, p_Bt, bt1, p_h1t,
                                                                 N_ITEMS, H1T, K3_TXT, K3_TXT / 32);

    // ego graph
    ego_init<<<(N_NODES * 16 + 255) / 256, 256>>>((const float4*)emb, out);
    fuse_items<<<(N_ITEMS + 63) / 64, 256>>>(out);

    int spmm_blocks = (nnz * 16 + 255) / 256;

    // layer 0: ego -> cur
    zero_nb<<<(N_NODES * 16 + 255) / 256, 256>>>();
    spmm_atomic<<<spmm_blocks, 256>>>(adj_row, adj_col, adj_val,
                                      (const float4*)p_ego, (float4*)p_nb, nnz);
    dense_layer<<<(N_NODES + 63) / 64, 256>>>(p_ego, p_nb, Wc0, bc0, p_cur, out, 64);

    // layer 1: cur -> out[:,128:192]
    zero_nb<<<(N_NODES * 16 + 255) / 256, 256>>>();
    spmm_atomic<<<spmm_blocks, 256>>>(adj_row, adj_col, adj_val,
                                      (const float4*)p_cur, (float4*)p_nb, nnz);
    dense_layer<<<(N_NODES + 63) / 64, 256>>>(p_cur, p_nb, Wc1, bc1, p_ego, out, 128);
}